// round 8
// baseline (speedup 1.0000x reference)
#include <cuda_runtime.h>

// Problem constants (fixed by the reference)
#define B       32
#define N       2048
#define OUTD    100
#define JSPLITS 16
#define JCHUNK  (N / JSPLITS)        // 128
#define BPG     4                    // batch rows per block
#define BGROUPS (B / BPG)            // 8
#define GRID    (JSPLITS * BGROUPS)  // 128 blocks
#define NT      512
#define NW      16
#define J_PER_WARP (JCHUNK / NW)     // 8
#define NPAIR   (OUTD / 2)           // 50 output pairs

// out[b,o] = sum_j rem[b,j] * W[j,o]
// rem[b,j] = (q[b,j] - float(N*c[b,j] + S_b))^2, c = (int)q, S_b = sum_j c[b,j]
// Exact vs reference: all integer partials < 2^24, so the reference's fp32
// reduce of the [N,N] broadcast equals the int32 closed form bit-for-bit.
// GEMV uses packed f32x2 over OUTPUT pairs: W 16B loads reinterpreted as two
// (w_o, w_o+1) pairs (no pack instr), rem duplicated in smem so LDS.64 gives
// the (r, r) operand directly. Fixed-order sums -> deterministic.

typedef unsigned long long u64;

__device__ float2       g_partial2[JSPLITS][B][NPAIR];   // (out_o, out_o+1)
__device__ unsigned int g_count[BGROUPS];                // zero-initialized

__device__ __forceinline__ void fma2(u64& d, u64 a, u64 b) {
    asm("fma.rn.f32x2 %0, %1, %2, %3;" : "=l"(d) : "l"(a), "l"(b), "l"(d));
}
__device__ __forceinline__ void add2(u64& d, u64 a) {
    asm("add.rn.f32x2 %0, %1, %2;" : "=l"(d) : "l"(a), "l"(d));
}

__global__ __launch_bounds__(NT, 1)
void fused_rowstat_gemv_kernel(const float* __restrict__ q,
                               const float* __restrict__ W,
                               float* __restrict__ out)
{
    __shared__ __align__(16) float2 remd[BPG][JCHUNK];    // (rem, rem) dup, 4 KB
    __shared__ __align__(16) float2 part_sh[NW][BPG * NPAIR];  // 25.6 KB
    __shared__ int qsum[NW];
    __shared__ int last_flag;

    const int tid  = threadIdx.x;
    const int wid  = tid >> 5;
    const int lane = tid & 31;
    const int s    = blockIdx.x & (JSPLITS - 1);   // j-split index
    const int bg   = blockIdx.x >> 4;              // batch-group index
    const int j0   = s * JCHUNK;

    // ---- Prefetch W as packed output-pairs (block-index-dependent only) ----
    const int g  = lane;                 // g<25 owns outputs 4g..4g+3
    const int jw = wid * J_PER_WARP;
    ulonglong2 wv[J_PER_WARP];           // .x = (w_{4g},w_{4g+1}), .y = (w_{4g+2},w_{4g+3})
    if (g < 25) {
        const float* Wg = W + (size_t)(j0 + jw) * OUTD + g * 4;   // 16B aligned
        #pragma unroll
        for (int jj = 0; jj < J_PER_WARP; ++jj)
            wv[jj] = *reinterpret_cast<const ulonglong2*>(Wg + jj * OUTD);
    }

    // ---- Phase 1: int row-sums (4 warps per row); keep this block's chunk ----
    const int r       = wid >> 2;
    const int quarter = wid & 3;
    const int i_need  = s >> 2;
    const bool owns_chunk = (quarter == (s & 3));
    float4 vkeep;
    {
        const float4* q4 = reinterpret_cast<const float4*>(q + (bg * BPG + r) * N);
        const int t = quarter * 32 + lane;
        int ss = 0;
        #pragma unroll
        for (int i = 0; i < 4; ++i) {
            float4 v = q4[t + 128 * i];
            ss += (int)v.x + (int)v.y + (int)v.z + (int)v.w;
            if (i == i_need) vkeep = v;
        }
        ss = __reduce_add_sync(0xFFFFFFFFu, ss);
        if (lane == 0) qsum[wid] = ss;
    }
    __syncthreads();

    // ---- Phase 2: owner warps compute their row's S from qsum (broadcast
    //      LDS, no extra barrier) and write duplicated rem pairs. ----
    if (owns_chunk) {
        const int S = qsum[4*r] + qsum[4*r+1] + qsum[4*r+2] + qsum[4*r+3];
        const float4 v = vkeep;
        int   c0 = (int)v.x, c1 = (int)v.y, c2 = (int)v.z, c3 = (int)v.w;
        float d0 = v.x - (float)(N * c0 + S);
        float d1 = v.y - (float)(N * c1 + S);
        float d2 = v.z - (float)(N * c2 + S);
        float d3 = v.w - (float)(N * c3 + S);
        const int col = lane * 4;                    // chunk-local column
        remd[r][col + 0] = make_float2(d0*d0, d0*d0);
        remd[r][col + 1] = make_float2(d1*d1, d1*d1);
        remd[r][col + 2] = make_float2(d2*d2, d2*d2);
        remd[r][col + 3] = make_float2(d3*d3, d3*d3);
    }
    __syncthreads();

    // ---- Phase 3: packed GEMV. Per jj: 4 broadcast LDS.64 + 8 fma.f32x2 ----
    if (g < 25) {
        u64 acc[BPG][2];
        #pragma unroll
        for (int rr = 0; rr < BPG; ++rr) { acc[rr][0] = 0ull; acc[rr][1] = 0ull; }

        #pragma unroll
        for (int jj = 0; jj < J_PER_WARP; ++jj) {
            const int col = jw + jj;
            u64 r0 = *reinterpret_cast<const u64*>(&remd[0][col]);
            u64 r1 = *reinterpret_cast<const u64*>(&remd[1][col]);
            u64 r2 = *reinterpret_cast<const u64*>(&remd[2][col]);
            u64 r3 = *reinterpret_cast<const u64*>(&remd[3][col]);
            fma2(acc[0][0], r0, wv[jj].x);  fma2(acc[0][1], r0, wv[jj].y);
            fma2(acc[1][0], r1, wv[jj].x);  fma2(acc[1][1], r1, wv[jj].y);
            fma2(acc[2][0], r2, wv[jj].x);  fma2(acc[2][1], r2, wv[jj].y);
            fma2(acc[3][0], r3, wv[jj].x);  fma2(acc[3][1], r3, wv[jj].y);
        }
        #pragma unroll
        for (int rr = 0; rr < BPG; ++rr) {
            *reinterpret_cast<u64*>(&part_sh[wid][rr * NPAIR + 2*g    ]) = acc[rr][0];
            *reinterpret_cast<u64*>(&part_sh[wid][rr * NPAIR + 2*g + 1]) = acc[rr][1];
        }
    }
    __syncthreads();

    // ---- Phase 4: reduce 16 warps (packed), publish split-K pair partial ----
    if (tid < BPG * NPAIR) {                         // 200 of 512 threads
        u64 a = 0ull;
        #pragma unroll
        for (int w = 0; w < NW; ++w)
            add2(a, *reinterpret_cast<const u64*>(&part_sh[w][tid]));
        const int rr = tid / NPAIR;
        const int pr = tid - rr * NPAIR;
        *reinterpret_cast<u64*>(&g_partial2[s][bg * BPG + rr][pr]) = a;
    }
    __threadfence();                                 // canonical split-K pattern
    __syncthreads();

    // ---- Phase 5: per-bgroup last block combines its 16 splits ----
    if (tid == 0) {
        unsigned old = atomicAdd(&g_count[bg], 1u);
        last_flag = (old == JSPLITS - 1);
        if (last_flag) g_count[bg] = 0;              // self-reset for graph replay
    }
    __syncthreads();

    if (last_flag && tid < BPG * NPAIR) {
        const int rr = tid / NPAIR;
        const int pr = tid - rr * NPAIR;
        const int b  = bg * BPG + rr;
        u64 a = 0ull;
        #pragma unroll
        for (int sp = 0; sp < JSPLITS; ++sp)         // 16 MLP'd LDG.64
            add2(a, *reinterpret_cast<const u64*>(&g_partial2[sp][b][pr]));
        *reinterpret_cast<u64*>(out + b * OUTD + 2 * pr) = a;   // 8B aligned
    }
}

extern "C" void kernel_launch(void* const* d_in, const int* in_sizes, int n_in,
                              void* d_out, int out_size)
{
    const float* q = (const float*)d_in[0];   // [32, 2048] f32
    const float* W = (const float*)d_in[1];   // [2048, 100] f32
    float* out = (float*)d_out;               // [32, 100] f32
    (void)in_sizes; (void)n_in; (void)out_size;

    fused_rowstat_gemv_kernel<<<GRID, NT>>>(q, W, out);
}